// round 12
// baseline (speedup 1.0000x reference)
#include <cuda_runtime.h>
#include <cuda_bf16.h>
#include <cstdint>

// Problem constants
#define BB 32      // batch
#define HH 512     // hidden
#define LL 2       // lstm layers
#define TT 20      // text_max_len
#define VV 10000   // vocab
#define SS 49      // spatial (7x7)

// ---------------- device scratch (no allocation allowed) ----------------
__device__ float g_keysT[BB * SS * HH];   // keys  transposed: [b][s][d]
__device__ float g_valsT[BB * SS * HH];   // values transposed: [b][s][d]
__device__ float g_H1[LL * BB * HH];      // h after LSTM (pre-attention-update)
__device__ float g_H2[LL * BB * HH];      // h after attention gate (input to next LSTM)
__device__ float g_C [LL * BB * HH];      // cell state
__device__ float g_q [LL * BB * HH];      // attention query
__device__ float g_attn[LL * BB * HH];    // attention context
__device__ float g_pred0[BB * HH];        // <SOS> embedding
__device__ unsigned long long g_amax[BB]; // packed argmax keys

// ---------------- helpers ----------------
__device__ __forceinline__ float sigmoidf_(float x) { return 1.0f / (1.0f + expf(-x)); }

__device__ __forceinline__ unsigned long long pack_key(float val, int v) {
    unsigned u = __float_as_uint(val);
    u = (u & 0x80000000u) ? ~u : (u | 0x80000000u);   // order-preserving map
    return (((unsigned long long)u) << 32) | (unsigned)(~(unsigned)v);
}

// packed dual-fp32 FMA, no packing movs: operands already packed in b64
__device__ __forceinline__ void ffma2p(unsigned long long &acc,
                                       unsigned long long w, unsigned long long x) {
    asm("fma.rn.f32x2 %0, %1, %2, %0;" : "+l"(acc) : "l"(w), "l"(x));
}
__device__ __forceinline__ float sum2(unsigned long long a) {
    float lo, hi;
    asm("mov.b64 {%0, %1}, %2;" : "=f"(lo), "=f"(hi) : "l"(a));
    return lo + hi;
}

// ---------------- K1: precompute keys/values (transposed) ----------------
__global__ void k_kv(const float* __restrict__ img,
                     const float* __restrict__ Wk, const float* __restrict__ bk,
                     const float* __restrict__ Wv, const float* __restrict__ bv) {
    __shared__ float wk_s[SS * SS];
    __shared__ float wv_s[SS * SS];
    for (int i = threadIdx.x; i < SS * SS; i += blockDim.x) {
        wk_s[i] = Wk[i];
        wv_s[i] = Wv[i];
    }
    __syncthreads();

    int idx = blockIdx.x * blockDim.x + threadIdx.x;
    int s = idx % SS;
    int d = (idx / SS) % HH;
    int b = idx / (SS * HH);

    const float* chan = img + (b * HH + d) * SS;
    float ak = 0.f, av = 0.f;
    #pragma unroll
    for (int sp = 0; sp < SS; ++sp) {
        float c = chan[sp];
        ak += c * wk_s[s * SS + sp];
        av += c * wv_s[s * SS + sp];
    }
    int o = (b * SS + s) * HH + d;
    g_keysT[o] = tanhf(ak + bk[s]);
    g_valsT[o] = tanhf(av + bv[s]);
}

// ---------------- K2: init state ----------------
__global__ void k_init(const float* __restrict__ pooled,
                       const float* __restrict__ embed,
                       const int* __restrict__ sos_ptr) {
    int idx = blockIdx.x * blockDim.x + threadIdx.x;
    int k = idx % HH;
    int b = (idx / HH) % BB;
    int l = idx / (HH * BB);
    float p = pooled[b * HH + k];
    g_H2[idx] = p;
    g_C[idx]  = p;
    if (l == 0) {
        int sos = sos_ptr[0];
        g_pred0[b * HH + k] = embed[sos * HH + k];
    }
    if (idx < BB) g_amax[idx] = 0ULL;
}

// ---------------- K3: logits GEMM, 512 thr, 64 rows/block, pipelined ----------------
// 157 blocks x 512 threads (16 warps, 16-way k-split, 2 quads each).
// Two row-groups of 32 processed back-to-back; prefetch bridges the emit phase.
__global__ void __launch_bounds__(512)
k_logits(int src_sel,
         const float* __restrict__ projW, const float* __restrict__ projb,
         float* __restrict__ res, int t, int do_argmax) {
    __shared__ float4 xs4[2][32][33];              // [buf][b][q]
    __shared__ float4 ws4[2][32][33];              // [buf][row][q]
    __shared__ float  red[8][32][17];              // [wpair][row][bi]
    __shared__ unsigned long long skey[16][33];    // [bi][row]

    const float* x = src_sel ? (g_H1 + BB * HH) : g_pred0;

    int tid  = threadIdx.x;
    int warp = tid >> 5;                 // 0..15
    int lane = tid & 31;                 // lane == vocab row within group
    int v0   = blockIdx.x * 64;

    unsigned long long acc[32];
    #pragma unroll
    for (int b = 0; b < 32; ++b) acc[b] = 0ULL;

    // prefetch chunk 0 (rg 0, k0 = 0): 2 f4 acts + 2 f4 weights per thread
    float4 ra[2], rw[2];
    #pragma unroll
    for (int i = 0; i < 2; ++i) {
        int f = tid + i * 512;
        int b = f >> 5, q = f & 31;
        ra[i] = *(const float4*)(x + b * HH + q * 4);
        int v = v0 + b; if (v >= VV) v = VV - 1;
        rw[i] = *(const float4*)(projW + (size_t)v * HH + q * 4);
    }

    for (int ch = 0; ch < 8; ++ch) {
        int rg = ch >> 2;
        int p  = ch & 1;
        #pragma unroll
        for (int i = 0; i < 2; ++i) {
            int f = tid + i * 512;
            xs4[p][f >> 5][f & 31] = ra[i];
            ws4[p][f >> 5][f & 31] = rw[i];
        }
        if (ch < 7) {
            int nrg = (ch + 1) >> 2;
            int nk0 = ((ch + 1) & 3) * 128;
            #pragma unroll
            for (int i = 0; i < 2; ++i) {
                int f = tid + i * 512;
                int b = f >> 5, q = f & 31;
                ra[i] = *(const float4*)(x + b * HH + nk0 + q * 4);
                int v = v0 + nrg * 32 + b; if (v >= VV) v = VV - 1;
                rw[i] = *(const float4*)(projW + (size_t)v * HH + nk0 + q * 4);
            }
        }
        __syncthreads();

        #pragma unroll
        for (int qq = 0; qq < 2; ++qq) {
            int q = warp * 2 + qq;
            ulonglong2 w = *reinterpret_cast<const ulonglong2*>(&ws4[p][lane][q]);
            #pragma unroll
            for (int b = 0; b < 32; ++b) {
                ulonglong2 xv = *reinterpret_cast<const ulonglong2*>(&xs4[p][b][q]);
                ffma2p(acc[b], w.x, xv.x);
                ffma2p(acc[b], w.y, xv.y);
            }
        }
        __syncthreads();

        // after chunks 3 and 7: reduce + emit this row-group, reset acc
        if ((ch & 3) == 3) {
            int vbase = v0 + rg * 32;
            for (int bh = 0; bh < 2; ++bh) {
                if (warp >= 8) {
                    #pragma unroll
                    for (int bi = 0; bi < 16; ++bi)
                        red[warp - 8][lane][bi] = sum2(acc[bh * 16 + bi]);
                }
                __syncthreads();
                if (warp < 8) {
                    #pragma unroll
                    for (int bi = 0; bi < 16; ++bi)
                        red[warp][lane][bi] += sum2(acc[bh * 16 + bi]);
                }
                __syncthreads();

                // 512 outputs: bi = tid&15, row = tid>>4
                int bi = tid & 15, row = tid >> 4;
                unsigned long long mybest = 0ULL;
                {
                    float val = 0.f;
                    #pragma unroll
                    for (int w = 0; w < 8; ++w) val += red[w][row][bi];
                    int v = vbase + row;
                    int b = bh * 16 + bi;
                    if (v < VV) {
                        val += projb[v];
                        res[b * (VV * TT) + v * TT + t] = val;
                        if (do_argmax) mybest = pack_key(val, v);
                    }
                }
                __syncthreads();

                if (do_argmax) {
                    skey[bi][row] = mybest;
                    __syncthreads();
                    if (tid < 16) {
                        unsigned long long m = 0ULL;
                        #pragma unroll
                        for (int r = 0; r < 32; ++r) {
                            unsigned long long k2 = skey[tid][r];
                            if (k2 > m) m = k2;
                        }
                        if (m) atomicMax(&g_amax[bh * 16 + tid], m);
                    }
                    __syncthreads();
                }
            }
            #pragma unroll
            for (int b = 0; b < 32; ++b) acc[b] = 0ULL;
        }
    }
}

// ---------------- K4: LSTM cell, 512 thr, pipelined, fused finalize ----------------
// 128 blocks x 512 threads (16 warps, 16-way k-split, 2 quads each).
// Tile = 4 units x 4 gates = 16 rows; lane -> (j = lane&15, bh = lane>>4).
// xsel: 0 -> g_pred0 ; 1 -> embed[argmax] ; 2 -> g_H1 layer 0
__global__ void __launch_bounds__(512)
k_lstm(int layer, int xsel, const float* __restrict__ embed,
       const float* __restrict__ Wih, const float* __restrict__ Whh,
       const float* __restrict__ bih, const float* __restrict__ bhh) {
    __shared__ float4 xs4[2][32][33];   // [buf][b][q]
    __shared__ float4 ws4[2][16][33];   // [buf][row j][q]
    __shared__ float  red[8][32][17];   // [wpair][b][j]
    __shared__ float  gv[16][33];       // [j][b]
    __shared__ int    vsel[BB];

    int tid  = threadIdx.x;   // 512
    int warp = tid >> 5;      // 0..15
    int lane = tid & 31;
    int j    = lane & 15;     // row within tile
    int bh   = lane >> 4;     // batch half
    int tile = blockIdx.x;

    if (layer == 1 && blockIdx.x == 0 && tid < BB) g_amax[tid] = 0ULL;
    if (xsel == 1 && tid < BB) vsel[tid] = (int)(~(unsigned)(g_amax[tid] & 0xffffffffULL));
    __syncthreads();

    const float* h_prev = g_H2 + layer * BB * HH;
    const float* x_base = (xsel == 2) ? g_H1 : g_pred0;
    const float* WihL = Wih + (size_t)layer * 4 * HH * HH;
    const float* WhhL = Whh + (size_t)layer * 4 * HH * HH;

    unsigned long long acc[16];
    #pragma unroll
    for (int bi = 0; bi < 16; ++bi) acc[bi] = 0ULL;

    // prefetch chunk 0 (mat = x, k0 = 0): acts 2 f4/thread, weights 1 f4/thread
    float4 ra[2], rw0;
    #pragma unroll
    for (int i = 0; i < 2; ++i) {
        int f = tid + i * 512;
        int b = f >> 5, q = f & 31;
        const float* src = (xsel == 1) ? (embed + (size_t)vsel[b] * HH)
                                       : (x_base + b * HH);
        ra[i] = *(const float4*)(src + q * 4);
    }
    {
        int r = tid >> 5, q = tid & 31;
        int grow = (r & 3) * HH + tile * 4 + (r >> 2);
        rw0 = *(const float4*)(WihL + (size_t)grow * HH + q * 4);
    }

    for (int ch = 0; ch < 8; ++ch) {
        int p = ch & 1;
        #pragma unroll
        for (int i = 0; i < 2; ++i) {
            int f = tid + i * 512;
            xs4[p][f >> 5][f & 31] = ra[i];
        }
        ws4[p][tid >> 5][tid & 31] = rw0;

        if (ch < 7) {
            int nmat = (ch + 1) >> 2;
            int nk0  = ((ch + 1) & 3) * 128;
            const float* wb = nmat ? WhhL : WihL;
            #pragma unroll
            for (int i = 0; i < 2; ++i) {
                int f = tid + i * 512;
                int b = f >> 5, q = f & 31;
                const float* src;
                if (nmat) src = h_prev + b * HH;
                else if (xsel == 1) src = embed + (size_t)vsel[b] * HH;
                else src = x_base + b * HH;
                ra[i] = *(const float4*)(src + nk0 + q * 4);
            }
            {
                int r = tid >> 5, q = tid & 31;
                int grow = (r & 3) * HH + tile * 4 + (r >> 2);
                rw0 = *(const float4*)(wb + (size_t)grow * HH + nk0 + q * 4);
            }
        }
        __syncthreads();

        #pragma unroll
        for (int qq = 0; qq < 2; ++qq) {
            int q = warp * 2 + qq;
            ulonglong2 w = *reinterpret_cast<const ulonglong2*>(&ws4[p][j][q]);
            #pragma unroll
            for (int bi = 0; bi < 16; ++bi) {
                ulonglong2 xv = *reinterpret_cast<const ulonglong2*>(&xs4[p][bh * 16 + bi][q]);
                ffma2p(acc[bi], w.x, xv.x);
                ffma2p(acc[bi], w.y, xv.y);
            }
        }
        __syncthreads();
    }

    // two-round k-slice reduction: warps 8-15 store, warps 0-7 add their own
    if (warp >= 8) {
        #pragma unroll
        for (int bi = 0; bi < 16; ++bi)
            red[warp - 8][bh * 16 + bi][j] = sum2(acc[bi]);
    }
    __syncthreads();
    if (warp < 8) {
        #pragma unroll
        for (int bi = 0; bi < 16; ++bi)
            red[warp][bh * 16 + bi][j] += sum2(acc[bi]);
    }
    __syncthreads();

    // gate pre-activations: 512 outputs, 1 per thread
    {
        int b = tid & 31, jj = tid >> 5;  // jj 0..15
        float val = 0.f;
        #pragma unroll
        for (int w = 0; w < 8; ++w) val += red[w][b][jj];
        int grow = (jj & 3) * HH + tile * 4 + (jj >> 2);
        val += bih[layer * 4 * HH + grow] + bhh[layer * 4 * HH + grow];
        gv[jj][b] = val;
    }
    __syncthreads();

    if (tid < 128) {
        int b = tid & 31, uu = tid >> 5;
        float vi = gv[uu * 4 + 0][b];
        float vf = gv[uu * 4 + 1][b];
        float vg = gv[uu * 4 + 2][b];
        float vo = gv[uu * 4 + 3][b];
        int u = tile * 4 + uu;
        int co = layer * BB * HH + b * HH + u;
        float c2 = sigmoidf_(vf) * g_C[co] + sigmoidf_(vi) * tanhf(vg);
        g_C[co]  = c2;
        g_H1[co] = sigmoidf_(vo) * tanhf(c2);
    }
}

// ---------------- K5: 32xN (N=512) GEMM + tanh ----------------
template <int MODE>
__global__ void k_gemm_tanh(const float* __restrict__ W1, const float* __restrict__ bias) {
    __shared__ float4 as4[32][17];
    __shared__ float4 bs4[32][17];
    __shared__ float4 wt[16][2][16];

    int l    = blockIdx.y;
    int tid  = threadIdx.x;    // 256
    int warp = tid >> 5;
    int lane = tid & 31;       // batch
    int j0   = blockIdx.x * 16;

    const float* A  = (MODE ? g_attn : g_H1) + l * BB * HH;
    const float* Bm = g_H1 + l * BB * HH;
    float*      out = (MODE ? g_H2 : g_q) + l * BB * HH;
    const int WS = MODE ? 2 * HH : HH;

    float4 acc[2];
    acc[0] = make_float4(0.f, 0.f, 0.f, 0.f);
    acc[1] = make_float4(0.f, 0.f, 0.f, 0.f);

    for (int kt = 0; kt < 8; ++kt) {
        int k0 = kt * 64;
        #pragma unroll
        for (int i = 0; i < 2; ++i) {
            int fid = tid + i * 256;
            int b = fid >> 4, q = fid & 15;
            as4[b][q] = *(const float4*)(A + b * HH + k0 + q * 4);
            if (MODE) bs4[b][q] = *(const float4*)(Bm + b * HH + k0 + q * 4);
        }
        {
            int r = tid >> 4, c = tid & 15;
            wt[r][0][c] = *(const float4*)(W1 + (j0 + r) * WS + k0 + c * 4);
            if (MODE) wt[r][1][c] = *(const float4*)(W1 + (j0 + r) * WS + HH + k0 + c * 4);
        }
        __syncthreads();

        int jr = warp * 2;
        #pragma unroll
        for (int q = 0; q < 16; ++q) {
            float4 av = as4[lane][q];
            float4 bv;
            if (MODE) bv = bs4[lane][q];
            #pragma unroll
            for (int jj = 0; jj < 2; ++jj) {
                float4 w = wt[jr + jj][0][q];
                acc[jj].x += w.x * av.x;  acc[jj].y += w.y * av.y;
                acc[jj].z += w.z * av.z;  acc[jj].w += w.w * av.w;
                if (MODE) {
                    float4 w2 = wt[jr + jj][1][q];
                    acc[jj].x += w2.x * bv.x;  acc[jj].y += w2.y * bv.y;
                    acc[jj].z += w2.z * bv.z;  acc[jj].w += w2.w * bv.w;
                }
            }
        }
        __syncthreads();
    }

    #pragma unroll
    for (int jj = 0; jj < 2; ++jj) {
        int jdx = j0 + warp * 2 + jj;
        float s = (acc[jj].x + acc[jj].y) + (acc[jj].z + acc[jj].w);
        out[lane * HH + jdx] = tanhf(s + bias[jdx]);
    }
}

// ---------------- K6: attention scores + softmax + context ----------------
__global__ void k_attn() {
    __shared__ float qs[HH];
    __shared__ float ssh[SS];
    __shared__ float wsh[SS];

    int b = blockIdx.x;
    int l = blockIdx.y;
    int tid = threadIdx.x;     // 256
    int warp = tid >> 5;
    int lane = tid & 31;

    qs[tid]       = g_q[(l * BB + b) * HH + tid];
    qs[tid + 256] = g_q[(l * BB + b) * HH + tid + 256];
    __syncthreads();

    for (int s = warp; s < SS; s += 8) {
        const float* krow = g_keysT + (b * SS + s) * HH;
        float sum = 0.f;
        #pragma unroll
        for (int i = 0; i < 4; ++i) {
            float4 kv = *(const float4*)(krow + lane * 4 + i * 128);
            float4 qv = *(const float4*)(qs   + lane * 4 + i * 128);
            sum += kv.x*qv.x + kv.y*qv.y + kv.z*qv.z + kv.w*qv.w;
        }
        #pragma unroll
        for (int off = 16; off; off >>= 1)
            sum += __shfl_xor_sync(0xffffffffu, sum, off);
        if (lane == 0) ssh[s] = sum / 7.0f;
    }
    __syncthreads();

    if (tid < 32) {
        float v0 = ssh[tid];
        float v1 = (tid + 32 < SS) ? ssh[tid + 32] : -3.4e38f;
        float m = fmaxf(v0, v1);
        #pragma unroll
        for (int off = 16; off; off >>= 1)
            m = fmaxf(m, __shfl_xor_sync(0xffffffffu, m, off));
        float e0 = expf(v0 - m);
        float e1 = (tid + 32 < SS) ? expf(v1 - m) : 0.f;
        float s = e0 + e1;
        #pragma unroll
        for (int off = 16; off; off >>= 1)
            s += __shfl_xor_sync(0xffffffffu, s, off);
        wsh[tid] = e0 / s;
        if (tid + 32 < SS) wsh[tid + 32] = e1 / s;
    }
    __syncthreads();

    #pragma unroll
    for (int r = 0; r < 2; ++r) {
        int d = tid + r * 256;
        float acc = 0.f;
        #pragma unroll
        for (int s = 0; s < SS; ++s)
            acc += wsh[s] * g_valsT[(b * SS + s) * HH + d];
        g_attn[(l * BB + b) * HH + d] = acc;
    }
}

// ---------------- host launcher ----------------
extern "C" void kernel_launch(void* const* d_in, const int* in_sizes, int n_in,
                              void* d_out, int out_size) {
    const float* img    = (const float*)d_in[0];
    const float* pooled = (const float*)d_in[1];
    const float* embed  = (const float*)d_in[2];
    const float* Wq     = (const float*)d_in[3];
    const float* bq     = (const float*)d_in[4];
    const float* Wk     = (const float*)d_in[5];
    const float* bk     = (const float*)d_in[6];
    const float* Wv     = (const float*)d_in[7];
    const float* bv     = (const float*)d_in[8];
    const float* Wih    = (const float*)d_in[9];
    const float* Whh    = (const float*)d_in[10];
    const float* bih    = (const float*)d_in[11];
    const float* bhh    = (const float*)d_in[12];
    const float* projW  = (const float*)d_in[13];
    const float* projb  = (const float*)d_in[14];
    const float* hattW  = (const float*)d_in[15];
    const float* hattb  = (const float*)d_in[16];
    const int*   sosp   = (const int*)d_in[17];
    float* res = (float*)d_out;

    k_kv<<<(BB * HH * SS) / 256, 256>>>(img, Wk, bk, Wv, bv);
    k_init<<<(LL * BB * HH) / 256, 256>>>(pooled, embed, sosp);

    // res[:, :, 0] from <SOS> embedding (no argmax)
    k_logits<<<157, 512>>>(0, projW, projb, res, 0, 0);

    for (int i = 0; i < TT - 1; ++i) {
        k_lstm<<<128, 512>>>(0, i == 0 ? 0 : 1, embed, Wih, Whh, bih, bhh);
        k_lstm<<<128, 512>>>(1, 2, embed, Wih, Whh, bih, bhh);
        k_logits<<<157, 512>>>(1, projW, projb, res, i + 1, (i < TT - 2) ? 1 : 0);

        if (i < TT - 2) {
            k_gemm_tanh<0><<<dim3(32, LL), 256>>>(Wq, bq);
            k_attn<<<dim3(BB, LL), 256>>>();
            k_gemm_tanh<1><<<dim3(32, LL), 256>>>(hattW, hattb);
        }
    }
}

// round 13
// speedup vs baseline: 1.2417x; 1.2417x over previous
#include <cuda_runtime.h>
#include <cuda_bf16.h>
#include <cstdint>

// Problem constants
#define BB 32      // batch
#define HH 512     // hidden
#define LL 2       // lstm layers
#define TT 20      // text_max_len
#define VV 10000   // vocab
#define SS 49      // spatial (7x7)

// Persistent-kernel geometry
#define NB 148     // grid blocks (all co-resident, 1/SM)
#define NT 512     // threads per block
#define LOGB 105   // blocks doing logits each step (105*96 = 10080 >= 10000)
#define ATT0 105   // first block of the attention group
#define NSUB 43    // attention group size (blocks 105..147)

// ---------------- device scratch (no allocation allowed) ----------------
__device__ float g_keysT[BB * SS * HH];   // keys  transposed: [b][s][d]
__device__ float g_valsT[BB * SS * HH];   // values transposed: [b][s][d]
__device__ float g_H1[LL * BB * HH];      // h after LSTM
__device__ float g_H2[LL * BB * HH];      // h after attention gate
__device__ float g_C [LL * BB * HH];      // cell state
__device__ float g_q [LL * BB * HH];      // attention query
__device__ float g_attn[LL * BB * HH];    // attention context
__device__ float g_pred0[BB * HH];        // <SOS> embedding
__device__ unsigned long long g_amax[BB]; // packed argmax keys

// barrier state (self-restoring across launches: counts return to 0,
// flags just flip; each block reads the current flag at kernel start)
__device__ unsigned g_bar_count;
__device__ volatile unsigned g_bar_flag;
__device__ unsigned g_sub_count;
__device__ volatile unsigned g_sub_flag;

// ---------------- helpers ----------------
__device__ __forceinline__ float sigmoidf_(float x) { return 1.0f / (1.0f + expf(-x)); }

__device__ __forceinline__ unsigned long long pack_key(float val, int v) {
    unsigned u = __float_as_uint(val);
    u = (u & 0x80000000u) ? ~u : (u | 0x80000000u);   // order-preserving map
    return (((unsigned long long)u) << 32) | (unsigned)(~(unsigned)v);
}

__device__ __forceinline__ void ffma2p(unsigned long long &acc,
                                       unsigned long long w, unsigned long long x) {
    asm("fma.rn.f32x2 %0, %1, %2, %0;" : "+l"(acc) : "l"(w), "l"(x));
}
__device__ __forceinline__ float sum2(unsigned long long a) {
    float lo, hi;
    asm("mov.b64 {%0, %1}, %2;" : "=f"(lo), "=f"(hi) : "l"(a));
    return lo + hi;
}

// sense-reversing grid barrier (all NB blocks)
__device__ __forceinline__ void grid_bar(unsigned &sense) {
    __syncthreads();
    if (threadIdx.x == 0) {
        __threadfence();
        unsigned t = atomicAdd(&g_bar_count, 1u);
        if (t == NB - 1u) {
            g_bar_count = 0u;
            __threadfence();
            g_bar_flag = sense ^ 1u;
        } else {
            while (g_bar_flag == sense) __nanosleep(32);
        }
        __threadfence();
    }
    __syncthreads();
    sense ^= 1u;
}

// sub-barrier among the NSUB attention blocks
__device__ __forceinline__ void sub_bar(unsigned &sense) {
    __syncthreads();
    if (threadIdx.x == 0) {
        __threadfence();
        unsigned t = atomicAdd(&g_sub_count, 1u);
        if (t == NSUB - 1u) {
            g_sub_count = 0u;
            __threadfence();
            g_sub_flag = sense ^ 1u;
        } else {
            while (g_sub_flag == sense) __nanosleep(32);
        }
        __threadfence();
    }
    __syncthreads();
    sense ^= 1u;
}

// ---------------- shared-memory layouts (phase-exclusive, one raw buffer) ----------------
struct SmemLogits {              // 67584 B
    float4 xs4[2][32][33];       // acts chunk     (red aliases nothing here)
    float4 ws4[2][32][33];       // weights chunk  (red+skey alias this after compute)
};
struct SmemLstm {                // 50816 B
    float4 xs4[2][32][33];       // acts   (red aliases this after compute)
    float4 ws4[2][16][33];       // weights (gv aliases this after reduction)
    int    vsel[BB];
};
struct SmemGemm {                // 33792 B
    float4 as4[32][17];
    float4 bs4[32][17];
    float4 wt[32][2][16];
};
struct SmemAttn {
    float qs[HH];
    float ssh[64];
    float wsh[64];
};
#define SMEM_BYTES 67584

// ---------------- phase: keys/values + state init ----------------
__device__ void ph_kv_init(void* smraw,
                           const float* __restrict__ img,
                           const float* __restrict__ pooled,
                           const float* __restrict__ embed, int sos,
                           const float* __restrict__ Wk, const float* __restrict__ bk,
                           const float* __restrict__ Wv, const float* __restrict__ bv) {
    float* wk_s = (float*)smraw;
    float* wv_s = wk_s + SS * SS;
    for (int i = threadIdx.x; i < SS * SS; i += NT) {
        wk_s[i] = Wk[i];
        wv_s[i] = Wv[i];
    }
    __syncthreads();

    const int N = BB * HH * SS;
    for (int idx = blockIdx.x * NT + threadIdx.x; idx < N; idx += NB * NT) {
        int s = idx % SS;
        int d = (idx / SS) % HH;
        int b = idx / (SS * HH);
        const float* chan = img + (b * HH + d) * SS;
        float ak = 0.f, av = 0.f;
        #pragma unroll
        for (int sp = 0; sp < SS; ++sp) {
            float c = chan[sp];
            ak += c * wk_s[s * SS + sp];
            av += c * wv_s[s * SS + sp];
        }
        int o = (b * SS + s) * HH + d;
        g_keysT[o] = tanhf(ak + bk[s]);
        g_valsT[o] = tanhf(av + bv[s]);
    }
    for (int idx = blockIdx.x * NT + threadIdx.x; idx < LL * BB * HH; idx += NB * NT) {
        int k = idx % HH;
        int b = (idx / HH) % BB;
        float p = pooled[b * HH + k];
        g_H2[idx] = p;
        g_C[idx]  = p;
        if (idx < BB * HH) g_pred0[idx] = embed[(size_t)sos * HH + k];
    }
}

// ---------------- phase: logits for one 32-row group ----------------
// 512 thr, 16-warp k-split (2 quads each), 4 pipelined chunks of 128 k.
__device__ void logits_group(SmemLogits* s, const float* __restrict__ x,
                             const float* __restrict__ projW,
                             const float* __restrict__ projb,
                             float* __restrict__ res, int v0, int t, int do_argmax) {
    int tid  = threadIdx.x;
    int warp = tid >> 5;
    int lane = tid & 31;                 // lane == vocab row within group

    unsigned long long acc[32];
    #pragma unroll
    for (int b = 0; b < 32; ++b) acc[b] = 0ULL;

    float4 ra[2], rw[2];
    #pragma unroll
    for (int i = 0; i < 2; ++i) {
        int f = tid + i * NT;
        int b = f >> 5, q = f & 31;
        ra[i] = *(const float4*)(x + b * HH + q * 4);
        int v = v0 + b; if (v >= VV) v = VV - 1;
        rw[i] = *(const float4*)(projW + (size_t)v * HH + q * 4);
    }

    for (int ch = 0; ch < 4; ++ch) {
        int p = ch & 1;
        #pragma unroll
        for (int i = 0; i < 2; ++i) {
            int f = tid + i * NT;
            s->xs4[p][f >> 5][f & 31] = ra[i];
            s->ws4[p][f >> 5][f & 31] = rw[i];
        }
        if (ch < 3) {
            int k0 = (ch + 1) * 128;
            #pragma unroll
            for (int i = 0; i < 2; ++i) {
                int f = tid + i * NT;
                int b = f >> 5, q = f & 31;
                ra[i] = *(const float4*)(x + b * HH + k0 + q * 4);
                int v = v0 + b; if (v >= VV) v = VV - 1;
                rw[i] = *(const float4*)(projW + (size_t)v * HH + k0 + q * 4);
            }
        }
        __syncthreads();

        #pragma unroll
        for (int qq = 0; qq < 2; ++qq) {
            int q = warp * 2 + qq;
            ulonglong2 w = *reinterpret_cast<const ulonglong2*>(&s->ws4[p][lane][q]);
            #pragma unroll
            for (int b = 0; b < 32; ++b) {
                ulonglong2 xv = *reinterpret_cast<const ulonglong2*>(&s->xs4[p][b][q]);
                ffma2p(acc[b], w.x, xv.x);
                ffma2p(acc[b], w.y, xv.y);
            }
        }
        __syncthreads();
    }

    // reduction + emit; red/skey alias ws4 (dead after last compute sync)
    float (*red)[32][17] = (float(*)[32][17])(s->ws4);
    unsigned long long (*skey)[33] =
        (unsigned long long(*)[33])((char*)s->ws4 + 8 * 32 * 17 * sizeof(float));

    for (int bh = 0; bh < 2; ++bh) {
        if (warp >= 8) {
            #pragma unroll
            for (int bi = 0; bi < 16; ++bi)
                red[warp - 8][lane][bi] = sum2(acc[bh * 16 + bi]);
        }
        __syncthreads();
        if (warp < 8) {
            #pragma unroll
            for (int bi = 0; bi < 16; ++bi)
                red[warp][lane][bi] += sum2(acc[bh * 16 + bi]);
        }
        __syncthreads();

        int bi = tid & 15, row = tid >> 4;
        unsigned long long mybest = 0ULL;
        {
            float val = 0.f;
            #pragma unroll
            for (int w = 0; w < 8; ++w) val += red[w][row][bi];
            int v = v0 + row;
            int b = bh * 16 + bi;
            if (v < VV) {
                val += projb[v];
                res[b * (VV * TT) + v * TT + t] = val;
                if (do_argmax) mybest = pack_key(val, v);
            }
        }
        __syncthreads();

        if (do_argmax) {
            skey[bi][row] = mybest;
            __syncthreads();
            if (tid < 16) {
                unsigned long long m = 0ULL;
                #pragma unroll
                for (int r = 0; r < 32; ++r) {
                    unsigned long long k2 = skey[tid][r];
                    if (k2 > m) m = k2;
                }
                if (m) atomicMax(&g_amax[bh * 16 + tid], m);
            }
            __syncthreads();
        }
    }
}

// ---------------- phase: LSTM cell (one layer), tile = 4 units x 4 gates ----------------
// xsel: 0 -> g_pred0 ; 1 -> embed[argmax] ; 2 -> g_H1 layer 0
__device__ void lstm_phase(SmemLstm* s, int tile, int layer, int xsel,
                           const float* __restrict__ embed,
                           const float* __restrict__ Wih, const float* __restrict__ Whh,
                           const float* __restrict__ bih, const float* __restrict__ bhh) {
    int tid  = threadIdx.x;
    int warp = tid >> 5;
    int lane = tid & 31;
    int j    = lane & 15;     // row within tile
    int bh   = lane >> 4;     // batch half

    if (xsel == 1 && tid < BB)
        s->vsel[tid] = (int)(~(unsigned)(g_amax[tid] & 0xffffffffULL));
    __syncthreads();

    const float* h_prev = g_H2 + layer * BB * HH;
    const float* x_base = (xsel == 2) ? g_H1 : g_pred0;
    const float* WihL = Wih + (size_t)layer * 4 * HH * HH;
    const float* WhhL = Whh + (size_t)layer * 4 * HH * HH;

    unsigned long long acc[16];
    #pragma unroll
    for (int bi = 0; bi < 16; ++bi) acc[bi] = 0ULL;

    float4 ra[2], rw0;
    #pragma unroll
    for (int i = 0; i < 2; ++i) {
        int f = tid + i * NT;
        int b = f >> 5, q = f & 31;
        const float* src = (xsel == 1) ? (embed + (size_t)s->vsel[b] * HH)
                                       : (x_base + b * HH);
        ra[i] = *(const float4*)(src + q * 4);
    }
    {
        int r = tid >> 5, q = tid & 31;
        int grow = (r & 3) * HH + tile * 4 + (r >> 2);
        rw0 = *(const float4*)(WihL + (size_t)grow * HH + q * 4);
    }

    for (int ch = 0; ch < 8; ++ch) {
        int p = ch & 1;
        #pragma unroll
        for (int i = 0; i < 2; ++i) {
            int f = tid + i * NT;
            s->xs4[p][f >> 5][f & 31] = ra[i];
        }
        s->ws4[p][tid >> 5][tid & 31] = rw0;

        if (ch < 7) {
            int nmat = (ch + 1) >> 2;
            int nk0  = ((ch + 1) & 3) * 128;
            const float* wb2 = nmat ? WhhL : WihL;
            #pragma unroll
            for (int i = 0; i < 2; ++i) {
                int f = tid + i * NT;
                int b = f >> 5, q = f & 31;
                const float* src;
                if (nmat) src = h_prev + b * HH;
                else if (xsel == 1) src = embed + (size_t)s->vsel[b] * HH;
                else src = x_base + b * HH;
                ra[i] = *(const float4*)(src + nk0 + q * 4);
            }
            {
                int r = tid >> 5, q = tid & 31;
                int grow = (r & 3) * HH + tile * 4 + (r >> 2);
                rw0 = *(const float4*)(wb2 + (size_t)grow * HH + nk0 + q * 4);
            }
        }
        __syncthreads();

        #pragma unroll
        for (int qq = 0; qq < 2; ++qq) {
            int q = warp * 2 + qq;
            ulonglong2 w = *reinterpret_cast<const ulonglong2*>(&s->ws4[p][j][q]);
            #pragma unroll
            for (int bi = 0; bi < 16; ++bi) {
                ulonglong2 xv = *reinterpret_cast<const ulonglong2*>(&s->xs4[p][bh * 16 + bi][q]);
                ffma2p(acc[bi], w.x, xv.x);
                ffma2p(acc[bi], w.y, xv.y);
            }
        }
        __syncthreads();
    }

    // red aliases xs4 (dead); gv aliases ws4 (dead)
    float (*red)[32][17] = (float(*)[32][17])(s->xs4);
    float (*gv)[33]      = (float(*)[33])(s->ws4);

    if (warp >= 8) {
        #pragma unroll
        for (int bi = 0; bi < 16; ++bi)
            red[warp - 8][bh * 16 + bi][j] = sum2(acc[bi]);
    }
    __syncthreads();
    if (warp < 8) {
        #pragma unroll
        for (int bi = 0; bi < 16; ++bi)
            red[warp][bh * 16 + bi][j] += sum2(acc[bi]);
    }
    __syncthreads();

    {
        int b = tid & 31, jj = tid >> 5;
        float val = 0.f;
        #pragma unroll
        for (int w = 0; w < 8; ++w) val += red[w][b][jj];
        int grow = (jj & 3) * HH + tile * 4 + (jj >> 2);
        val += bih[layer * 4 * HH + grow] + bhh[layer * 4 * HH + grow];
        gv[jj][b] = val;
    }
    __syncthreads();

    if (tid < 128) {
        int b = tid & 31, uu = tid >> 5;
        float vi = gv[uu * 4 + 0][b];
        float vf = gv[uu * 4 + 1][b];
        float vg = gv[uu * 4 + 2][b];
        float vo = gv[uu * 4 + 3][b];
        int u = tile * 4 + uu;
        int co = layer * BB * HH + b * HH + u;
        float c2 = sigmoidf_(vf) * g_C[co] + sigmoidf_(vi) * tanhf(vg);
        g_C[co]  = c2;
        g_H1[co] = sigmoidf_(vo) * tanhf(c2);
    }
    __syncthreads();
}

// ---------------- phase: 32xN GEMM + tanh (tile = 32 out rows), 512 thr ----------------
// MODE 0 (q):     out = g_q,  in = g_H1,            W row stride 512
// MODE 1 (h-upd): out = g_H2, in = [g_attn ; g_H1], W row stride 1024
template <int MODE>
__device__ void gemm_phase(SmemGemm* s, int t,
                           const float* __restrict__ W1, const float* __restrict__ bias) {
    int l  = t >> 4;
    int j0 = (t & 15) * 32;
    int tid  = threadIdx.x;    // 512
    int warp = tid >> 5;       // 0..15, 2 rows each
    int lane = tid & 31;       // batch

    const float* A  = (MODE ? g_attn : g_H1) + l * BB * HH;
    const float* Bm = g_H1 + l * BB * HH;
    float*      out = (MODE ? g_H2 : g_q) + l * BB * HH;
    const int WS = MODE ? 2 * HH : HH;

    float4 acc[2];
    acc[0] = make_float4(0.f, 0.f, 0.f, 0.f);
    acc[1] = make_float4(0.f, 0.f, 0.f, 0.f);

    for (int kt = 0; kt < 8; ++kt) {
        int k0 = kt * 64;
        {
            int b = tid >> 4, q = tid & 15;
            s->as4[b][q] = *(const float4*)(A + b * HH + k0 + q * 4);
            if (MODE) s->bs4[b][q] = *(const float4*)(Bm + b * HH + k0 + q * 4);
        }
        {
            int r = tid >> 4, c = tid & 15;
            s->wt[r][0][c] = *(const float4*)(W1 + (size_t)(j0 + r) * WS + k0 + c * 4);
            if (MODE) s->wt[r][1][c] = *(const float4*)(W1 + (size_t)(j0 + r) * WS + HH + k0 + c * 4);
        }
        __syncthreads();

        int jr = warp * 2;
        #pragma unroll
        for (int q = 0; q < 16; ++q) {
            float4 av = s->as4[lane][q];
            float4 bv;
            if (MODE) bv = s->bs4[lane][q];
            #pragma unroll
            for (int jj = 0; jj < 2; ++jj) {
                float4 w = s->wt[jr + jj][0][q];
                acc[jj].x += w.x * av.x;  acc[jj].y += w.y * av.y;
                acc[jj].z += w.z * av.z;  acc[jj].w += w.w * av.w;
                if (MODE) {
                    float4 w2 = s->wt[jr + jj][1][q];
                    acc[jj].x += w2.x * bv.x;  acc[jj].y += w2.y * bv.y;
                    acc[jj].z += w2.z * bv.z;  acc[jj].w += w2.w * bv.w;
                }
            }
        }
        __syncthreads();
    }

    #pragma unroll
    for (int jj = 0; jj < 2; ++jj) {
        int jdx = j0 + warp * 2 + jj;
        float sv = (acc[jj].x + acc[jj].y) + (acc[jj].z + acc[jj].w);
        out[lane * HH + jdx] = tanhf(sv + bias[jdx]);
    }
}

// ---------------- phase: attention for one (l, b) pair, 512 thr ----------------
__device__ void attn_one(SmemAttn* s, int l, int b) {
    int tid  = threadIdx.x;
    int warp = tid >> 5;      // 0..15
    int lane = tid & 31;

    s->qs[tid] = g_q[(l * BB + b) * HH + tid];
    __syncthreads();

    for (int sp = warp; sp < SS; sp += 16) {
        const float* krow = g_keysT + (b * SS + sp) * HH;
        float sum = 0.f;
        #pragma unroll
        for (int i = 0; i < 4; ++i) {
            float4 kv = *(const float4*)(krow  + lane * 4 + i * 128);
            float4 qv = *(const float4*)(s->qs + lane * 4 + i * 128);
            sum += kv.x*qv.x + kv.y*qv.y + kv.z*qv.z + kv.w*qv.w;
        }
        #pragma unroll
        for (int off = 16; off; off >>= 1)
            sum += __shfl_xor_sync(0xffffffffu, sum, off);
        if (lane == 0) s->ssh[sp] = sum / 7.0f;
    }
    __syncthreads();

    if (tid < 32) {
        float v0 = s->ssh[tid];
        float v1 = (tid + 32 < SS) ? s->ssh[tid + 32] : -3.4e38f;
        float m = fmaxf(v0, v1);
        #pragma unroll
        for (int off = 16; off; off >>= 1)
            m = fmaxf(m, __shfl_xor_sync(0xffffffffu, m, off));
        float e0 = expf(v0 - m);
        float e1 = (tid + 32 < SS) ? expf(v1 - m) : 0.f;
        float sm = e0 + e1;
        #pragma unroll
        for (int off = 16; off; off >>= 1)
            sm += __shfl_xor_sync(0xffffffffu, sm, off);
        s->wsh[tid] = e0 / sm;
        if (tid + 32 < SS) s->wsh[tid + 32] = e1 / sm;
    }
    __syncthreads();

    {
        int d = tid;           // HH == NT == 512
        float a = 0.f;
        #pragma unroll
        for (int sp = 0; sp < SS; ++sp)
            a += s->wsh[sp] * g_valsT[(b * SS + sp) * HH + d];
        g_attn[(l * BB + b) * HH + d] = a;
    }
    __syncthreads();
}

// ---------------- the single persistent kernel ----------------
__global__ void __launch_bounds__(NT, 1)
k_all(const float* __restrict__ img, const float* __restrict__ pooled,
      const float* __restrict__ embed,
      const float* __restrict__ Wq, const float* __restrict__ bq,
      const float* __restrict__ Wk, const float* __restrict__ bk,
      const float* __restrict__ Wv, const float* __restrict__ bv,
      const float* __restrict__ Wih, const float* __restrict__ Whh,
      const float* __restrict__ bih, const float* __restrict__ bhh,
      const float* __restrict__ projW, const float* __restrict__ projb,
      const float* __restrict__ hattW, const float* __restrict__ hattb,
      const int* __restrict__ sosp, float* __restrict__ res) {
    __shared__ __align__(16) unsigned char smraw[SMEM_BYTES];
    int wb = blockIdx.x;

    // read barrier senses BEFORE any arrival (no flip can precede this read)
    unsigned sense  = g_bar_flag;
    unsigned ssense = g_sub_flag;

    // phase A: keys/values + state init
    ph_kv_init(smraw, img, pooled, embed, sosp[0], Wk, bk, Wv, bv);
    grid_bar(sense);

    // phase B: res[:, :, 0] from <SOS> embedding (no argmax)
    if (wb < LOGB) {
        for (int g = 0; g < 3; ++g)
            logits_group((SmemLogits*)smraw, g_pred0, projW, projb, res,
                         wb * 96 + g * 32, 0, 0);
    }
    grid_bar(sense);

    for (int i = 0; i < TT - 1; ++i) {
        // P1: LSTM layer 0 (reads g_amax from previous step when i > 0)
        if (wb < 128)
            lstm_phase((SmemLstm*)smraw, wb, 0, (i == 0) ? 0 : 1,
                       embed, Wih, Whh, bih, bhh);
        grid_bar(sense);

        // P2: LSTM layer 1; block 128 resets the argmax accumulator
        if (wb < 128)
            lstm_phase((SmemLstm*)smraw, wb, 1, 2, embed, Wih, Whh, bih, bhh);
        else if (wb == 128 && threadIdx.x < BB)
            g_amax[threadIdx.x] = 0ULL;
        grid_bar(sense);

        // P3 (split): blocks 0..104 logits; blocks 105..147 attention chain
        if (wb < LOGB) {
            const float* xx = g_H1 + BB * HH;    // top-layer output
            for (int g = 0; g < 3; ++g)
                logits_group((SmemLogits*)smraw, xx, projW, projb, res,
                             wb * 96 + g * 32, i + 1, (i < TT - 2) ? 1 : 0);
        } else if (i < TT - 2) {
            int t = wb - ATT0;                   // 0..42
            if (t < 32) gemm_phase<0>((SmemGemm*)smraw, t, Wq, bq);
            sub_bar(ssense);
            {
                int p = t;
                attn_one((SmemAttn*)smraw, p >> 5, p & 31);
                int p2 = t + NSUB;
                if (p2 < 2 * BB) attn_one((SmemAttn*)smraw, p2 >> 5, p2 & 31);
            }
            sub_bar(ssense);
            if (t < 32) gemm_phase<1>((SmemGemm*)smraw, t, hattW, hattb);
        }
        grid_bar(sense);
    }
}

// ---------------- host launcher ----------------
extern "C" void kernel_launch(void* const* d_in, const int* in_sizes, int n_in,
                              void* d_out, int out_size) {
    const float* img    = (const float*)d_in[0];
    const float* pooled = (const float*)d_in[1];
    const float* embed  = (const float*)d_in[2];
    const float* Wq     = (const float*)d_in[3];
    const float* bq     = (const float*)d_in[4];
    const float* Wk     = (const float*)d_in[5];
    const float* bk     = (const float*)d_in[6];
    const float* Wv     = (const float*)d_in[7];
    const float* bv     = (const float*)d_in[8];
    const float* Wih    = (const float*)d_in[9];
    const float* Whh    = (const float*)d_in[10];
    const float* bih    = (const float*)d_in[11];
    const float* bhh    = (const float*)d_in[12];
    const float* projW  = (const float*)d_in[13];
    const float* projb  = (const float*)d_in[14];
    const float* hattW  = (const float*)d_in[15];
    const float* hattb  = (const float*)d_in[16];
    const int*   sosp   = (const int*)d_in[17];
    float* res = (float*)d_out;

    k_all<<<NB, NT>>>(img, pooled, embed, Wq, bq, Wk, bk, Wv, bv,
                      Wih, Whh, bih, bhh, projW, projb, hattW, hattb, sosp, res);
}

// round 14
// speedup vs baseline: 1.2502x; 1.0069x over previous
#include <cuda_runtime.h>
#include <cuda_bf16.h>
#include <cstdint>

// Problem constants
#define BB 32      // batch
#define HH 512     // hidden
#define LL 2       // lstm layers
#define TT 20      // text_max_len
#define VV 10000   // vocab
#define SS 49      // spatial (7x7)

// Persistent-kernel geometry
#define NB 148     // grid blocks (1/SM)
#define NT 512     // threads per block
#define LOGB 105   // blocks doing logits each step (105*96 = 10080 >= 10000)
#define ATT0 105   // first block of the attention group
#define NSUB 43    // attention group size (blocks 105..147)

// Dynamic shared memory layout (bytes)
#define OFF_XS   0                      // float4 [3][32][33] = 50688
#define OFF_WS   50688                  // float4 [3][32][33] = 50688 (lstm uses [3][16][33])
#define OFF_RED  101376                 // float [8][32][33] = 33792 (lstm: [8][32][17])
#define OFF_SKEY 135168                 // ull [32][17] = 4352   (lstm: gv float[16][33])
#define OFF_VSEL 139520                 // int [32] = 128
#define DYN_BYTES 139648

// ---------------- device scratch ----------------
__device__ float g_keysT[BB * SS * HH];
__device__ float g_valsT[BB * SS * HH];
__device__ float g_H1[LL * BB * HH];
__device__ float g_H2[LL * BB * HH];
__device__ float g_C [LL * BB * HH];
__device__ float g_q [LL * BB * HH];
__device__ float g_attn[LL * BB * HH];
__device__ float g_pred0[BB * HH];
__device__ unsigned long long g_amax[BB];

__device__ unsigned g_bar_count;
__device__ volatile unsigned g_bar_flag;
__device__ unsigned g_sub_count;
__device__ volatile unsigned g_sub_flag;

// ---------------- helpers ----------------
__device__ __forceinline__ float sigmoidf_(float x) { return 1.0f / (1.0f + expf(-x)); }

__device__ __forceinline__ unsigned long long pack_key(float val, int v) {
    unsigned u = __float_as_uint(val);
    u = (u & 0x80000000u) ? ~u : (u | 0x80000000u);
    return (((unsigned long long)u) << 32) | (unsigned)(~(unsigned)v);
}
__device__ __forceinline__ void ffma2p(unsigned long long &acc,
                                       unsigned long long w, unsigned long long x) {
    asm("fma.rn.f32x2 %0, %1, %2, %0;" : "+l"(acc) : "l"(w), "l"(x));
}
__device__ __forceinline__ float sum2(unsigned long long a) {
    float lo, hi;
    asm("mov.b64 {%0, %1}, %2;" : "=f"(lo), "=f"(hi) : "l"(a));
    return lo + hi;
}
__device__ __forceinline__ void cpa16(void* dst, const void* src) {
    unsigned d = (unsigned)__cvta_generic_to_shared(dst);
    asm volatile("cp.async.cg.shared.global [%0], [%1], 16;" :: "r"(d), "l"(src) : "memory");
}
__device__ __forceinline__ void cp_commit() { asm volatile("cp.async.commit_group;" ::: "memory"); }
__device__ __forceinline__ void cp_wait2()  { asm volatile("cp.async.wait_group 2;" ::: "memory"); }

__device__ __forceinline__ void grid_bar(unsigned &sense) {
    __syncthreads();
    if (threadIdx.x == 0) {
        __threadfence();
        unsigned t = atomicAdd(&g_bar_count, 1u);
        if (t == NB - 1u) {
            g_bar_count = 0u;
            __threadfence();
            g_bar_flag = sense ^ 1u;
        } else {
            while (g_bar_flag == sense) __nanosleep(32);
        }
        __threadfence();
    }
    __syncthreads();
    sense ^= 1u;
}
__device__ __forceinline__ void sub_bar(unsigned &sense) {
    __syncthreads();
    if (threadIdx.x == 0) {
        __threadfence();
        unsigned t = atomicAdd(&g_sub_count, 1u);
        if (t == NSUB - 1u) {
            g_sub_count = 0u;
            __threadfence();
            g_sub_flag = sense ^ 1u;
        } else {
            while (g_sub_flag == sense) __nanosleep(32);
        }
        __threadfence();
    }
    __syncthreads();
    sense ^= 1u;
}

// ---------------- phase: keys/values + state init ----------------
__device__ void ph_kv_init(char* sm,
                           const float* __restrict__ img,
                           const float* __restrict__ pooled,
                           const float* __restrict__ embed, int sos,
                           const float* __restrict__ Wk, const float* __restrict__ bk,
                           const float* __restrict__ Wv, const float* __restrict__ bv) {
    float* wk_s = (float*)sm;
    float* wv_s = wk_s + SS * SS;
    for (int i = threadIdx.x; i < SS * SS; i += NT) {
        wk_s[i] = Wk[i];
        wv_s[i] = Wv[i];
    }
    __syncthreads();

    const int N = BB * HH * SS;
    for (int idx = blockIdx.x * NT + threadIdx.x; idx < N; idx += NB * NT) {
        int s = idx % SS;
        int d = (idx / SS) % HH;
        int b = idx / (SS * HH);
        const float* chan = img + (b * HH + d) * SS;
        float ak = 0.f, av = 0.f;
        #pragma unroll
        for (int sp = 0; sp < SS; ++sp) {
            float c = chan[sp];
            ak += c * wk_s[s * SS + sp];
            av += c * wv_s[s * SS + sp];
        }
        int o = (b * SS + s) * HH + d;
        g_keysT[o] = tanhf(ak + bk[s]);
        g_valsT[o] = tanhf(av + bv[s]);
    }
    for (int idx = blockIdx.x * NT + threadIdx.x; idx < LL * BB * HH; idx += NB * NT) {
        int k = idx % HH;
        int b = (idx / HH) % BB;
        float p = pooled[b * HH + k];
        g_H2[idx] = p;
        g_C[idx]  = p;
        if (idx < BB * HH) g_pred0[idx] = embed[(size_t)sos * HH + k];
    }
}

// ---------------- phase: logits (96 rows/block = 3 groups of 32), cp.async 3-deep ----------------
__device__ void logits_phase(char* sm, const float* __restrict__ x,
                             const float* __restrict__ projW,
                             const float* __restrict__ projb,
                             float* __restrict__ res, int vblock0, int t, int do_argmax) {
    float4 (*xs)[32][33] = (float4(*)[32][33])(sm + OFF_XS);
    float4 (*ws)[32][33] = (float4(*)[32][33])(sm + OFF_WS);
    float  (*red)[32][33] = (float(*)[32][33])(sm + OFF_RED);
    unsigned long long (*skey)[17] = (unsigned long long(*)[17])(sm + OFF_SKEY);

    int tid = threadIdx.x, warp = tid >> 5, lane = tid & 31;

    unsigned long long acc[32];
    #pragma unroll
    for (int b = 0; b < 32; ++b) acc[b] = 0ULL;

    // issue chunk c (c in 0..11): group g = c>>2, k-chunk kc = c&3
    #define LG_ISSUE(c_) do {                                                   \
        int g_ = (c_) >> 2, kc_ = (c_) & 3, buf_ = (c_) % 3, k0_ = kc_ * 128;   \
        _Pragma("unroll")                                                        \
        for (int i_ = 0; i_ < 2; ++i_) {                                         \
            int f_ = tid + i_ * NT;                                              \
            int b_ = f_ >> 5, q_ = f_ & 31;                                      \
            cpa16(&xs[buf_][b_][q_], x + b_ * HH + k0_ + q_ * 4);                \
            int v_ = vblock0 + g_ * 32 + b_; if (v_ >= VV) v_ = VV - 1;          \
            cpa16(&ws[buf_][b_][q_], projW + (size_t)v_ * HH + k0_ + q_ * 4);    \
        } } while (0)

    LG_ISSUE(0); cp_commit();
    LG_ISSUE(1); cp_commit();
    LG_ISSUE(2); cp_commit();

    for (int c = 0; c < 12; ++c) {
        cp_wait2();
        __syncthreads();
        int buf = c % 3;

        #pragma unroll
        for (int qq = 0; qq < 2; ++qq) {
            int q = warp * 2 + qq;
            ulonglong2 w = *(const ulonglong2*)&ws[buf][lane][q];
            #pragma unroll
            for (int s = 0; s < 4; ++s) {
                ulonglong2 xv[8];
                #pragma unroll
                for (int k2 = 0; k2 < 8; ++k2)
                    xv[k2] = *(const ulonglong2*)&xs[buf][s * 8 + k2][q];
                #pragma unroll
                for (int k2 = 0; k2 < 8; ++k2) {
                    ffma2p(acc[s * 8 + k2], w.x, xv[k2].x);
                    ffma2p(acc[s * 8 + k2], w.y, xv[k2].y);
                }
            }
        }
        __syncthreads();

        if (c + 3 < 12) LG_ISSUE(c + 3);
        cp_commit();   // empty group when nothing issued (keeps wait_group 2 uniform)

        if ((c & 3) == 3) {   // emit group g = c>>2
            int vbase = vblock0 + (c >> 2) * 32;
            if (warp >= 8) {
                #pragma unroll
                for (int bi = 0; bi < 32; ++bi)
                    red[warp - 8][lane][bi] = sum2(acc[bi]);
            }
            __syncthreads();
            if (warp < 8) {
                #pragma unroll
                for (int bi = 0; bi < 32; ++bi)
                    red[warp][lane][bi] += sum2(acc[bi]);
            }
            __syncthreads();

            // 1024 outputs: rep r -> o = tid + r*512; b = o&31 (same both reps), row = o>>5
            int b = tid & 31;
            unsigned long long mybest = 0ULL;
            #pragma unroll
            for (int rep = 0; rep < 2; ++rep) {
                int row = (tid >> 5) + rep * 16;
                float val = 0.f;
                #pragma unroll
                for (int w = 0; w < 8; ++w) val += red[w][row][b];
                int v = vbase + row;
                if (v < VV) {
                    val += projb[v];
                    res[b * (VV * TT) + v * TT + t] = val;
                    if (do_argmax) {
                        unsigned long long key = pack_key(val, v);
                        if (key > mybest) mybest = key;
                    }
                }
            }
            if (do_argmax) {
                skey[b][tid >> 5] = mybest;
                __syncthreads();
                if (tid < 32) {
                    unsigned long long m = 0ULL;
                    #pragma unroll
                    for (int r = 0; r < 16; ++r) {
                        unsigned long long k2 = skey[tid][r];
                        if (k2 > m) m = k2;
                    }
                    if (m) atomicMax(&g_amax[tid], m);
                }
            }
            __syncthreads();
            #pragma unroll
            for (int bb = 0; bb < 32; ++bb) acc[bb] = 0ULL;
        }
    }
    #undef LG_ISSUE
}

// ---------------- phase: LSTM cell (tile = 4 units x 4 gates), cp.async 3-deep ----------------
// xsel: 0 -> g_pred0 ; 1 -> embed[argmax] ; 2 -> g_H1 layer 0
__device__ void lstm_phase(char* sm, int tile, int layer, int xsel,
                           const float* __restrict__ embed,
                           const float* __restrict__ Wih, const float* __restrict__ Whh,
                           const float* __restrict__ bih, const float* __restrict__ bhh) {
    float4 (*xs)[32][33] = (float4(*)[32][33])(sm + OFF_XS);
    float4 (*ws)[16][33] = (float4(*)[16][33])(sm + OFF_WS);
    float  (*red)[32][17] = (float(*)[32][17])(sm + OFF_RED);
    float  (*gv)[33]      = (float(*)[33])(sm + OFF_SKEY);
    int*   vsel           = (int*)(sm + OFF_VSEL);

    int tid  = threadIdx.x;
    int warp = tid >> 5;
    int lane = tid & 31;
    int j    = lane & 15;
    int bh   = lane >> 4;

    if (xsel == 1 && tid < BB)
        vsel[tid] = (int)(~(unsigned)(g_amax[tid] & 0xffffffffULL));
    __syncthreads();

    const float* h_prev = g_H2 + layer * BB * HH;
    const float* x_base = (xsel == 2) ? g_H1 : g_pred0;
    const float* WihL = Wih + (size_t)layer * 4 * HH * HH;
    const float* WhhL = Whh + (size_t)layer * 4 * HH * HH;

    unsigned long long acc[16];
    #pragma unroll
    for (int bi = 0; bi < 16; ++bi) acc[bi] = 0ULL;

    #define LS_ISSUE(c_) do {                                                     \
        int mat_ = (c_) >> 2, k0_ = ((c_) & 3) * 128, buf_ = (c_) % 3;            \
        const float* wb_ = mat_ ? WhhL : WihL;                                    \
        _Pragma("unroll")                                                          \
        for (int i_ = 0; i_ < 2; ++i_) {                                           \
            int f_ = tid + i_ * NT;                                               \
            int b_ = f_ >> 5, q_ = f_ & 31;                                        \
            const float* src_;                                                     \
            if (mat_) src_ = h_prev + b_ * HH;                                     \
            else if (xsel == 1) src_ = embed + (size_t)vsel[b_] * HH;               \
            else src_ = x_base + b_ * HH;                                          \
            cpa16(&xs[buf_][b_][q_], src_ + k0_ + q_ * 4);                         \
        }                                                                          \
        { int r_ = tid >> 5, q_ = tid & 31;                                        \
          int grow_ = (r_ & 3) * HH + tile * 4 + (r_ >> 2);                        \
          cpa16(&ws[buf_][r_][q_], wb_ + (size_t)grow_ * HH + k0_ + q_ * 4); }     \
    } while (0)

    LS_ISSUE(0); cp_commit();
    LS_ISSUE(1); cp_commit();
    LS_ISSUE(2); cp_commit();

    for (int c = 0; c < 8; ++c) {
        cp_wait2();
        __syncthreads();
        int buf = c % 3;

        #pragma unroll
        for (int qq = 0; qq < 2; ++qq) {
            int q = warp * 2 + qq;
            ulonglong2 w = *(const ulonglong2*)&ws[buf][j][q];
            #pragma unroll
            for (int s = 0; s < 2; ++s) {
                ulonglong2 xv[8];
                #pragma unroll
                for (int k2 = 0; k2 < 8; ++k2)
                    xv[k2] = *(const ulonglong2*)&xs[buf][bh * 16 + s * 8 + k2][q];
                #pragma unroll
                for (int k2 = 0; k2 < 8; ++k2) {
                    ffma2p(acc[s * 8 + k2], w.x, xv[k2].x);
                    ffma2p(acc[s * 8 + k2], w.y, xv[k2].y);
                }
            }
        }
        __syncthreads();

        if (c + 3 < 8) LS_ISSUE(c + 3);
        cp_commit();
    }
    #undef LS_ISSUE

    if (warp >= 8) {
        #pragma unroll
        for (int bi = 0; bi < 16; ++bi)
            red[warp - 8][bh * 16 + bi][j] = sum2(acc[bi]);
    }
    __syncthreads();
    if (warp < 8) {
        #pragma unroll
        for (int bi = 0; bi < 16; ++bi)
            red[warp][bh * 16 + bi][j] += sum2(acc[bi]);
    }
    __syncthreads();

    {
        int b = tid & 31, jj = tid >> 5;
        float val = 0.f;
        #pragma unroll
        for (int w = 0; w < 8; ++w) val += red[w][b][jj];
        int grow = (jj & 3) * HH + tile * 4 + (jj >> 2);
        val += bih[layer * 4 * HH + grow] + bhh[layer * 4 * HH + grow];
        gv[jj][b] = val;
    }
    __syncthreads();

    if (tid < 128) {
        int b = tid & 31, uu = tid >> 5;
        float vi = gv[uu * 4 + 0][b];
        float vf = gv[uu * 4 + 1][b];
        float vg = gv[uu * 4 + 2][b];
        float vo = gv[uu * 4 + 3][b];
        int u = tile * 4 + uu;
        int co = layer * BB * HH + b * HH + u;
        float c2 = sigmoidf_(vf) * g_C[co] + sigmoidf_(vi) * tanhf(vg);
        g_C[co]  = c2;
        g_H1[co] = sigmoidf_(vo) * tanhf(c2);
    }
    __syncthreads();
}

// ---------------- phase: 32xN GEMM + tanh (tile = 32 out rows) ----------------
struct SmemGemm {
    float4 as4[32][17];
    float4 bs4[32][17];
    float4 wt[32][2][16];
};
template <int MODE>
__device__ void gemm_phase(char* sm, int t,
                           const float* __restrict__ W1, const float* __restrict__ bias) {
    SmemGemm* s = (SmemGemm*)sm;
    int l  = t >> 4;
    int j0 = (t & 15) * 32;
    int tid  = threadIdx.x;
    int warp = tid >> 5;
    int lane = tid & 31;

    const float* A  = (MODE ? g_attn : g_H1) + l * BB * HH;
    const float* Bm = g_H1 + l * BB * HH;
    float*      out = (MODE ? g_H2 : g_q) + l * BB * HH;
    const int WS = MODE ? 2 * HH : HH;

    float4 acc[2];
    acc[0] = make_float4(0.f, 0.f, 0.f, 0.f);
    acc[1] = make_float4(0.f, 0.f, 0.f, 0.f);

    for (int kt = 0; kt < 8; ++kt) {
        int k0 = kt * 64;
        {
            int b = tid >> 4, q = tid & 15;
            s->as4[b][q] = *(const float4*)(A + b * HH + k0 + q * 4);
            if (MODE) s->bs4[b][q] = *(const float4*)(Bm + b * HH + k0 + q * 4);
        }
        {
            int r = tid >> 4, c = tid & 15;
            s->wt[r][0][c] = *(const float4*)(W1 + (size_t)(j0 + r) * WS + k0 + c * 4);
            if (MODE) s->wt[r][1][c] = *(const float4*)(W1 + (size_t)(j0 + r) * WS + HH + k0 + c * 4);
        }
        __syncthreads();

        int jr = warp * 2;
        #pragma unroll
        for (int q = 0; q < 16; ++q) {
            float4 av = s->as4[lane][q];
            float4 bv;
            if (MODE) bv = s->bs4[lane][q];
            #pragma unroll
            for (int jj = 0; jj < 2; ++jj) {
                float4 w = s->wt[jr + jj][0][q];
                acc[jj].x += w.x * av.x;  acc[jj].y += w.y * av.y;
                acc[jj].z += w.z * av.z;  acc[jj].w += w.w * av.w;
                if (MODE) {
                    float4 w2 = s->wt[jr + jj][1][q];
                    acc[jj].x += w2.x * bv.x;  acc[jj].y += w2.y * bv.y;
                    acc[jj].z += w2.z * bv.z;  acc[jj].w += w2.w * bv.w;
                }
            }
        }
        __syncthreads();
    }

    #pragma unroll
    for (int jj = 0; jj < 2; ++jj) {
        int jdx = j0 + warp * 2 + jj;
        float sv = (acc[jj].x + acc[jj].y) + (acc[jj].z + acc[jj].w);
        out[lane * HH + jdx] = tanhf(sv + bias[jdx]);
    }
}

// ---------------- phase: attention for one (l, b) pair ----------------
struct SmemAttn {
    float qs[HH];
    float ssh[64];
    float wsh[64];
};
__device__ void attn_one(char* sm, int l, int b) {
    SmemAttn* s = (SmemAttn*)sm;
    int tid  = threadIdx.x;
    int warp = tid >> 5;
    int lane = tid & 31;

    s->qs[tid] = g_q[(l * BB + b) * HH + tid];
    __syncthreads();

    for (int sp = warp; sp < SS; sp += 16) {
        const float* krow = g_keysT + (b * SS + sp) * HH;
        float sum = 0.f;
        #pragma unroll
        for (int i = 0; i < 4; ++i) {
            float4 kv = *(const float4*)(krow  + lane * 4 + i * 128);
            float4 qv = *(const float4*)(s->qs + lane * 4 + i * 128);
            sum += kv.x*qv.x + kv.y*qv.y + kv.z*qv.z + kv.w*qv.w;
        }
        #pragma unroll
        for (int off = 16; off; off >>= 1)
            sum += __shfl_xor_sync(0xffffffffu, sum, off);
        if (lane == 0) s->ssh[sp] = sum / 7.0f;
    }
    __syncthreads();

    if (tid < 32) {
        float v0 = s->ssh[tid];
        float v1 = (tid + 32 < SS) ? s->ssh[tid + 32] : -3.4e38f;
        float m = fmaxf(v0, v1);
        #pragma unroll
        for (int off = 16; off; off >>= 1)
            m = fmaxf(m, __shfl_xor_sync(0xffffffffu, m, off));
        float e0 = expf(v0 - m);
        float e1 = (tid + 32 < SS) ? expf(v1 - m) : 0.f;
        float sm2 = e0 + e1;
        #pragma unroll
        for (int off = 16; off; off >>= 1)
            sm2 += __shfl_xor_sync(0xffffffffu, sm2, off);
        s->wsh[tid] = e0 / sm2;
        if (tid + 32 < SS) s->wsh[tid + 32] = e1 / sm2;
    }
    __syncthreads();

    {
        int d = tid;
        float a = 0.f;
        #pragma unroll
        for (int sp = 0; sp < SS; ++sp)
            a += s->wsh[sp] * g_valsT[(b * SS + sp) * HH + d];
        g_attn[(l * BB + b) * HH + d] = a;
    }
    __syncthreads();
}

// ---------------- the single persistent kernel ----------------
extern "C" __global__ void __launch_bounds__(NT, 1)
k_all(const float* __restrict__ img, const float* __restrict__ pooled,
      const float* __restrict__ embed,
      const float* __restrict__ Wq, const float* __restrict__ bq,
      const float* __restrict__ Wk, const float* __restrict__ bk,
      const float* __restrict__ Wv, const float* __restrict__ bv,
      const float* __restrict__ Wih, const float* __restrict__ Whh,
      const float* __restrict__ bih, const float* __restrict__ bhh,
      const float* __restrict__ projW, const float* __restrict__ projb,
      const float* __restrict__ hattW, const float* __restrict__ hattb,
      const int* __restrict__ sosp, float* __restrict__ res) {
    extern __shared__ __align__(16) char dynsm[];
    int wb = blockIdx.x;

    unsigned sense  = g_bar_flag;
    unsigned ssense = g_sub_flag;

    // phase A: keys/values + state init
    ph_kv_init(dynsm, img, pooled, embed, sosp[0], Wk, bk, Wv, bv);
    grid_bar(sense);

    // phase B: res[:, :, 0] from <SOS> embedding (no argmax)
    if (wb < LOGB)
        logits_phase(dynsm, g_pred0, projW, projb, res, wb * 96, 0, 0);
    grid_bar(sense);

    for (int i = 0; i < TT - 1; ++i) {
        // P1: LSTM layer 0
        if (wb < 128)
            lstm_phase(dynsm, wb, 0, (i == 0) ? 0 : 1, embed, Wih, Whh, bih, bhh);
        grid_bar(sense);

        // P2: LSTM layer 1; block 128 resets argmax accumulator
        if (wb < 128)
            lstm_phase(dynsm, wb, 1, 2, embed, Wih, Whh, bih, bhh);
        else if (wb == 128 && threadIdx.x < BB)
            g_amax[threadIdx.x] = 0ULL;
        grid_bar(sense);

        // P3 (split): blocks 0..104 logits; blocks 105..147 attention chain
        if (wb < LOGB) {
            logits_phase(dynsm, g_H1 + BB * HH, projW, projb, res,
                         wb * 96, i + 1, (i < TT - 2) ? 1 : 0);
        } else if (i < TT - 2) {
            int t = wb - ATT0;
            if (t < 32) gemm_phase<0>(dynsm, t, Wq, bq);
            sub_bar(ssense);
            {
                attn_one(dynsm, t >> 5, t & 31);
                int p2 = t + NSUB;
                if (p2 < 2 * BB) attn_one(dynsm, p2 >> 5, p2 & 31);
            }
            sub_bar(ssense);
            if (t < 32) gemm_phase<1>(dynsm, t, hattW, hattb);
        }
        grid_bar(sense);
    }
}

// ---------------- host launcher ----------------
extern "C" void kernel_launch(void* const* d_in, const int* in_sizes, int n_in,
                              void* d_out, int out_size) {
    const float* img    = (const float*)d_in[0];
    const float* pooled = (const float*)d_in[1];
    const float* embed  = (const float*)d_in[2];
    const float* Wq     = (const float*)d_in[3];
    const float* bq     = (const float*)d_in[4];
    const float* Wk     = (const float*)d_in[5];
    const float* bk     = (const float*)d_in[6];
    const float* Wv     = (const float*)d_in[7];
    const float* bv     = (const float*)d_in[8];
    const float* Wih    = (const float*)d_in[9];
    const float* Whh    = (const float*)d_in[10];
    const float* bih    = (const float*)d_in[11];
    const float* bhh    = (const float*)d_in[12];
    const float* projW  = (const float*)d_in[13];
    const float* projb  = (const float*)d_in[14];
    const float* hattW  = (const float*)d_in[15];
    const float* hattb  = (const float*)d_in[16];
    const int*   sosp   = (const int*)d_in[17];
    float* res = (float*)d_out;

    static int attr_set = 0;
    if (!attr_set) {
        cudaFuncSetAttribute(k_all, cudaFuncAttributeMaxDynamicSharedMemorySize, DYN_BYTES);
        attr_set = 1;
    }
    k_all<<<NB, NT, DYN_BYTES>>>(img, pooled, embed, Wq, bq, Wk, bk, Wv, bv,
                                 Wih, Whh, bih, bhh, projW, projb,
                                 hattW, hattb, sosp, res);
}

// round 15
// speedup vs baseline: 1.2789x; 1.0229x over previous
#include <cuda_runtime.h>
#include <cuda_bf16.h>
#include <cstdint>

// Problem constants
#define BB 32      // batch
#define HH 512     // hidden
#define LL 2       // lstm layers
#define TT 20      // text_max_len
#define VV 10000   // vocab
#define SS 49      // spatial (7x7)

// Persistent-kernel geometry
#define NB 148     // grid blocks (1/SM)
#define NT 512     // threads per block
#define LOGB 105   // blocks doing logits each step (105*96 = 10080 >= 10000)
#define ATT0 105   // first block of the attention group
#define NSUB 43    // attention group size (blocks 105..147)

// Dynamic shared memory layout (bytes)
#define OFF_XS   0                      // float4 [3][32][33] = 50688
#define OFF_WS   50688                  // float4 [3][32][33] = 50688 (lstm uses [3][16][33])
#define OFF_RED  101376                 // float [8][32][33] = 33792 (lstm: [8][32][17])
#define OFF_SKEY 135168                 // ull [32][17] = 4352   (lstm: gv float[16][33])
#define OFF_VSEL 139520                 // int [32] = 128
#define DYN_BYTES 139648

// ---------------- device scratch ----------------
__device__ float g_keysT[BB * SS * HH];
__device__ float g_valsT[BB * SS * HH];
__device__ float g_H1[LL * BB * HH];
__device__ float g_H2[LL * BB * HH];
__device__ float g_C [LL * BB * HH];
__device__ float g_q [LL * BB * HH];
__device__ float g_attn[LL * BB * HH];
__device__ float g_pred0[BB * HH];
__device__ unsigned long long g_amax[BB];

__device__ unsigned g_bar_count;
__device__ volatile unsigned g_bar_flag;
__device__ unsigned g_sub_count;
__device__ volatile unsigned g_sub_flag;

// ---------------- helpers ----------------
__device__ __forceinline__ float sigmoidf_(float x) { return 1.0f / (1.0f + expf(-x)); }

__device__ __forceinline__ unsigned long long pack_key(float val, int v) {
    unsigned u = __float_as_uint(val);
    u = (u & 0x80000000u) ? ~u : (u | 0x80000000u);
    return (((unsigned long long)u) << 32) | (unsigned)(~(unsigned)v);
}
__device__ __forceinline__ void ffma2p(unsigned long long &acc,
                                       unsigned long long w, unsigned long long x) {
    asm("fma.rn.f32x2 %0, %1, %2, %0;" : "+l"(acc) : "l"(w), "l"(x));
}
__device__ __forceinline__ float sum2(unsigned long long a) {
    float lo, hi;
    asm("mov.b64 {%0, %1}, %2;" : "=f"(lo), "=f"(hi) : "l"(a));
    return lo + hi;
}
__device__ __forceinline__ void cpa16(void* dst, const void* src) {
    unsigned d = (unsigned)__cvta_generic_to_shared(dst);
    asm volatile("cp.async.cg.shared.global [%0], [%1], 16;" :: "r"(d), "l"(src) : "memory");
}
__device__ __forceinline__ void cp_commit() { asm volatile("cp.async.commit_group;" ::: "memory"); }
__device__ __forceinline__ void cp_wait2()  { asm volatile("cp.async.wait_group 2;" ::: "memory"); }

__device__ __forceinline__ void grid_bar(unsigned &sense) {
    __syncthreads();
    if (threadIdx.x == 0) {
        __threadfence();
        unsigned t = atomicAdd(&g_bar_count, 1u);
        if (t == NB - 1u) {
            g_bar_count = 0u;
            __threadfence();
            g_bar_flag = sense ^ 1u;
        } else {
            while (g_bar_flag == sense) __nanosleep(32);
        }
        __threadfence();
    }
    __syncthreads();
    sense ^= 1u;
}
__device__ __forceinline__ void sub_bar(unsigned &sense) {
    __syncthreads();
    if (threadIdx.x == 0) {
        __threadfence();
        unsigned t = atomicAdd(&g_sub_count, 1u);
        if (t == NSUB - 1u) {
            g_sub_count = 0u;
            __threadfence();
            g_sub_flag = sense ^ 1u;
        } else {
            while (g_sub_flag == sense) __nanosleep(32);
        }
        __threadfence();
    }
    __syncthreads();
    sense ^= 1u;
}

// ---------------- phase: keys/values + state init ----------------
__device__ void ph_kv_init(char* sm,
                           const float* __restrict__ img,
                           const float* __restrict__ pooled,
                           const float* __restrict__ embed, int sos,
                           const float* __restrict__ Wk, const float* __restrict__ bk,
                           const float* __restrict__ Wv, const float* __restrict__ bv) {
    float* wk_s = (float*)sm;
    float* wv_s = wk_s + SS * SS;
    for (int i = threadIdx.x; i < SS * SS; i += NT) {
        wk_s[i] = Wk[i];
        wv_s[i] = Wv[i];
    }
    __syncthreads();

    const int N = BB * HH * SS;
    for (int idx = blockIdx.x * NT + threadIdx.x; idx < N; idx += NB * NT) {
        int s = idx % SS;
        int d = (idx / SS) % HH;
        int b = idx / (SS * HH);
        const float* chan = img + (b * HH + d) * SS;
        float ak = 0.f, av = 0.f;
        #pragma unroll
        for (int sp = 0; sp < SS; ++sp) {
            float c = chan[sp];
            ak += c * wk_s[s * SS + sp];
            av += c * wv_s[s * SS + sp];
        }
        int o = (b * SS + s) * HH + d;
        g_keysT[o] = tanhf(ak + bk[s]);
        g_valsT[o] = tanhf(av + bv[s]);
    }
    for (int idx = blockIdx.x * NT + threadIdx.x; idx < LL * BB * HH; idx += NB * NT) {
        int k = idx % HH;
        int b = (idx / HH) % BB;
        float p = pooled[b * HH + k];
        g_H2[idx] = p;
        g_C[idx]  = p;
        if (idx < BB * HH) g_pred0[idx] = embed[(size_t)sos * HH + k];
    }
}

// ---------------- phase: logits (96 rows/block = 3 groups of 32), cp.async 3-deep ----------------
// Register-tiled: lane = (rp = lane&7, bp = lane>>3); thread computes rows rp+8i (i<4),
// batches j*4+bp (j<8): per qq 12 LDS.128 feed 64 FFMA2.
__device__ void logits_phase(char* sm, const float* __restrict__ x,
                             const float* __restrict__ projW,
                             const float* __restrict__ projb,
                             float* __restrict__ res, int vblock0, int t, int do_argmax) {
    float4 (*xs)[32][33] = (float4(*)[32][33])(sm + OFF_XS);
    float4 (*ws)[32][33] = (float4(*)[32][33])(sm + OFF_WS);
    float  (*red)[32][33] = (float(*)[32][33])(sm + OFF_RED);
    unsigned long long (*skey)[17] = (unsigned long long(*)[17])(sm + OFF_SKEY);

    int tid = threadIdx.x, warp = tid >> 5, lane = tid & 31;
    int rp = lane & 7;     // row phase: rows rp + 8i
    int bp = lane >> 3;    // batch phase: batches j*4 + bp

    unsigned long long acc[32];   // acc[i*8+j]
    #pragma unroll
    for (int b = 0; b < 32; ++b) acc[b] = 0ULL;

    #define LG_ISSUE(c_) do {                                                   \
        int g_ = (c_) >> 2, kc_ = (c_) & 3, buf_ = (c_) % 3, k0_ = kc_ * 128;   \
        _Pragma("unroll")                                                        \
        for (int i_ = 0; i_ < 2; ++i_) {                                         \
            int f_ = tid + i_ * NT;                                              \
            int b_ = f_ >> 5, q_ = f_ & 31;                                      \
            cpa16(&xs[buf_][b_][q_], x + b_ * HH + k0_ + q_ * 4);                \
            int v_ = vblock0 + g_ * 32 + b_; if (v_ >= VV) v_ = VV - 1;          \
            cpa16(&ws[buf_][b_][q_], projW + (size_t)v_ * HH + k0_ + q_ * 4);    \
        } } while (0)

    LG_ISSUE(0); cp_commit();
    LG_ISSUE(1); cp_commit();
    LG_ISSUE(2); cp_commit();

    for (int c = 0; c < 12; ++c) {
        cp_wait2();
        __syncthreads();
        int buf = c % 3;

        #pragma unroll
        for (int qq = 0; qq < 2; ++qq) {
            int q = warp * 2 + qq;
            ulonglong2 w[4];
            #pragma unroll
            for (int i = 0; i < 4; ++i)
                w[i] = *(const ulonglong2*)&ws[buf][rp + 8 * i][q];
            #pragma unroll
            for (int jg = 0; jg < 2; ++jg) {
                ulonglong2 xv[4];
                #pragma unroll
                for (int j = 0; j < 4; ++j)
                    xv[j] = *(const ulonglong2*)&xs[buf][(jg * 4 + j) * 4 + bp][q];
                #pragma unroll
                for (int i = 0; i < 4; ++i)
                    #pragma unroll
                    for (int j = 0; j < 4; ++j) {
                        ffma2p(acc[i * 8 + jg * 4 + j], w[i].x, xv[j].x);
                        ffma2p(acc[i * 8 + jg * 4 + j], w[i].y, xv[j].y);
                    }
            }
        }
        __syncthreads();

        if (c + 3 < 12) LG_ISSUE(c + 3);
        cp_commit();   // empty group when nothing issued (keeps wait_group 2 uniform)

        if ((c & 3) == 3) {   // emit group g = c>>2
            int vbase = vblock0 + (c >> 2) * 32;
            if (warp >= 8) {
                #pragma unroll
                for (int i = 0; i < 4; ++i)
                    #pragma unroll
                    for (int j = 0; j < 8; ++j)
                        red[warp - 8][rp + 8 * i][j * 4 + bp] = sum2(acc[i * 8 + j]);
            }
            __syncthreads();
            if (warp < 8) {
                #pragma unroll
                for (int i = 0; i < 4; ++i)
                    #pragma unroll
                    for (int j = 0; j < 8; ++j)
                        red[warp][rp + 8 * i][j * 4 + bp] += sum2(acc[i * 8 + j]);
            }
            __syncthreads();

            // 1024 outputs: rep r -> b = tid&31 (same both reps), row = (tid>>5)+rep*16
            int b = tid & 31;
            unsigned long long mybest = 0ULL;
            #pragma unroll
            for (int rep = 0; rep < 2; ++rep) {
                int row = (tid >> 5) + rep * 16;
                float val = 0.f;
                #pragma unroll
                for (int w2 = 0; w2 < 8; ++w2) val += red[w2][row][b];
                int v = vbase + row;
                if (v < VV) {
                    val += projb[v];
                    res[b * (VV * TT) + v * TT + t] = val;
                    if (do_argmax) {
                        unsigned long long key = pack_key(val, v);
                        if (key > mybest) mybest = key;
                    }
                }
            }
            if (do_argmax) {
                skey[b][tid >> 5] = mybest;
                __syncthreads();
                if (tid < 32) {
                    unsigned long long m = 0ULL;
                    #pragma unroll
                    for (int r = 0; r < 16; ++r) {
                        unsigned long long k2 = skey[tid][r];
                        if (k2 > m) m = k2;
                    }
                    if (m) atomicMax(&g_amax[tid], m);
                }
            }
            __syncthreads();
            #pragma unroll
            for (int bb = 0; bb < 32; ++bb) acc[bb] = 0ULL;
        }
    }
    #undef LG_ISSUE
}

// ---------------- phase: LSTM cell (tile = 4 units x 4 gates), cp.async 3-deep ----------------
// Register-tiled: lane = (rp = lane&3, bp = lane>>2); thread computes rows rp+4i (i<4),
// batches j*8+bp (j<4): per qq 8 LDS.128 feed 32 FFMA2.
// xsel: 0 -> g_pred0 ; 1 -> embed[argmax] ; 2 -> g_H1 layer 0
__device__ void lstm_phase(char* sm, int tile, int layer, int xsel,
                           const float* __restrict__ embed,
                           const float* __restrict__ Wih, const float* __restrict__ Whh,
                           const float* __restrict__ bih, const float* __restrict__ bhh) {
    float4 (*xs)[32][33] = (float4(*)[32][33])(sm + OFF_XS);
    float4 (*ws)[16][33] = (float4(*)[16][33])(sm + OFF_WS);
    float  (*red)[32][17] = (float(*)[32][17])(sm + OFF_RED);
    float  (*gv)[33]      = (float(*)[33])(sm + OFF_SKEY);
    int*   vsel           = (int*)(sm + OFF_VSEL);

    int tid  = threadIdx.x;
    int warp = tid >> 5;
    int lane = tid & 31;
    int rp   = lane & 3;   // rows rp + 4i
    int bp   = lane >> 2;  // batches j*8 + bp

    if (xsel == 1 && tid < BB)
        vsel[tid] = (int)(~(unsigned)(g_amax[tid] & 0xffffffffULL));
    __syncthreads();

    const float* h_prev = g_H2 + layer * BB * HH;
    const float* x_base = (xsel == 2) ? g_H1 : g_pred0;
    const float* WihL = Wih + (size_t)layer * 4 * HH * HH;
    const float* WhhL = Whh + (size_t)layer * 4 * HH * HH;

    unsigned long long acc[16];   // acc[i*4+j]
    #pragma unroll
    for (int bi = 0; bi < 16; ++bi) acc[bi] = 0ULL;

    #define LS_ISSUE(c_) do {                                                     \
        int mat_ = (c_) >> 2, k0_ = ((c_) & 3) * 128, buf_ = (c_) % 3;            \
        const float* wb_ = mat_ ? WhhL : WihL;                                    \
        _Pragma("unroll")                                                          \
        for (int i_ = 0; i_ < 2; ++i_) {                                           \
            int f_ = tid + i_ * NT;                                               \
            int b_ = f_ >> 5, q_ = f_ & 31;                                        \
            const float* src_;                                                     \
            if (mat_) src_ = h_prev + b_ * HH;                                     \
            else if (xsel == 1) src_ = embed + (size_t)vsel[b_] * HH;               \
            else src_ = x_base + b_ * HH;                                          \
            cpa16(&xs[buf_][b_][q_], src_ + k0_ + q_ * 4);                         \
        }                                                                          \
        { int r_ = tid >> 5, q_ = tid & 31;                                        \
          int grow_ = (r_ & 3) * HH + tile * 4 + (r_ >> 2);                        \
          cpa16(&ws[buf_][r_][q_], wb_ + (size_t)grow_ * HH + k0_ + q_ * 4); }     \
    } while (0)

    LS_ISSUE(0); cp_commit();
    LS_ISSUE(1); cp_commit();
    LS_ISSUE(2); cp_commit();

    for (int c = 0; c < 8; ++c) {
        cp_wait2();
        __syncthreads();
        int buf = c % 3;

        #pragma unroll
        for (int qq = 0; qq < 2; ++qq) {
            int q = warp * 2 + qq;
            ulonglong2 w[4], xv[4];
            #pragma unroll
            for (int i = 0; i < 4; ++i)
                w[i] = *(const ulonglong2*)&ws[buf][rp + 4 * i][q];
            #pragma unroll
            for (int j = 0; j < 4; ++j)
                xv[j] = *(const ulonglong2*)&xs[buf][j * 8 + bp][q];
            #pragma unroll
            for (int i = 0; i < 4; ++i)
                #pragma unroll
                for (int j = 0; j < 4; ++j) {
                    ffma2p(acc[i * 4 + j], w[i].x, xv[j].x);
                    ffma2p(acc[i * 4 + j], w[i].y, xv[j].y);
                }
        }
        __syncthreads();

        if (c + 3 < 8) LS_ISSUE(c + 3);
        cp_commit();
    }
    #undef LS_ISSUE

    if (warp >= 8) {
        #pragma unroll
        for (int i = 0; i < 4; ++i)
            #pragma unroll
            for (int j = 0; j < 4; ++j)
                red[warp - 8][j * 8 + bp][rp + 4 * i] = sum2(acc[i * 4 + j]);
    }
    __syncthreads();
    if (warp < 8) {
        #pragma unroll
        for (int i = 0; i < 4; ++i)
            #pragma unroll
            for (int j = 0; j < 4; ++j)
                red[warp][j * 8 + bp][rp + 4 * i] += sum2(acc[i * 4 + j]);
    }
    __syncthreads();

    {
        int b = tid & 31, jj = tid >> 5;  // jj 0..15
        float val = 0.f;
        #pragma unroll
        for (int w2 = 0; w2 < 8; ++w2) val += red[w2][b][jj];
        int grow = (jj & 3) * HH + tile * 4 + (jj >> 2);
        val += bih[layer * 4 * HH + grow] + bhh[layer * 4 * HH + grow];
        gv[jj][b] = val;
    }
    __syncthreads();

    if (tid < 128) {
        int b = tid & 31, uu = tid >> 5;
        float vi = gv[uu * 4 + 0][b];
        float vf = gv[uu * 4 + 1][b];
        float vg = gv[uu * 4 + 2][b];
        float vo = gv[uu * 4 + 3][b];
        int u = tile * 4 + uu;
        int co = layer * BB * HH + b * HH + u;
        float c2 = sigmoidf_(vf) * g_C[co] + sigmoidf_(vi) * tanhf(vg);
        g_C[co]  = c2;
        g_H1[co] = sigmoidf_(vo) * tanhf(c2);
    }
    __syncthreads();
}

// ---------------- phase: 32xN GEMM + tanh (tile = 32 out rows) ----------------
struct SmemGemm {
    float4 as4[32][17];
    float4 bs4[32][17];
    float4 wt[32][2][16];
};
template <int MODE>
__device__ void gemm_phase(char* sm, int t,
                           const float* __restrict__ W1, const float* __restrict__ bias) {
    SmemGemm* s = (SmemGemm*)sm;
    int l  = t >> 4;
    int j0 = (t & 15) * 32;
    int tid  = threadIdx.x;
    int warp = tid >> 5;
    int lane = tid & 31;

    const float* A  = (MODE ? g_attn : g_H1) + l * BB * HH;
    const float* Bm = g_H1 + l * BB * HH;
    float*      out = (MODE ? g_H2 : g_q) + l * BB * HH;
    const int WS = MODE ? 2 * HH : HH;

    float4 acc[2];
    acc[0] = make_float4(0.f, 0.f, 0.f, 0.f);
    acc[1] = make_float4(0.f, 0.f, 0.f, 0.f);

    for (int kt = 0; kt < 8; ++kt) {
        int k0 = kt * 64;
        {
            int b = tid >> 4, q = tid & 15;
            s->as4[b][q] = *(const float4*)(A + b * HH + k0 + q * 4);
            if (MODE) s->bs4[b][q] = *(const float4*)(Bm + b * HH + k0 + q * 4);
        }
        {
            int r = tid >> 4, c = tid & 15;
            s->wt[r][0][c] = *(const float4*)(W1 + (size_t)(j0 + r) * WS + k0 + c * 4);
            if (MODE) s->wt[r][1][c] = *(const float4*)(W1 + (size_t)(j0 + r) * WS + HH + k0 + c * 4);
        }
        __syncthreads();

        int jr = warp * 2;
        #pragma unroll
        for (int q = 0; q < 16; ++q) {
            float4 av = s->as4[lane][q];
            float4 bv;
            if (MODE) bv = s->bs4[lane][q];
            #pragma unroll
            for (int jj = 0; jj < 2; ++jj) {
                float4 w = s->wt[jr + jj][0][q];
                acc[jj].x += w.x * av.x;  acc[jj].y += w.y * av.y;
                acc[jj].z += w.z * av.z;  acc[jj].w += w.w * av.w;
                if (MODE) {
                    float4 w2 = s->wt[jr + jj][1][q];
                    acc[jj].x += w2.x * bv.x;  acc[jj].y += w2.y * bv.y;
                    acc[jj].z += w2.z * bv.z;  acc[jj].w += w2.w * bv.w;
                }
            }
        }
        __syncthreads();
    }

    #pragma unroll
    for (int jj = 0; jj < 2; ++jj) {
        int jdx = j0 + warp * 2 + jj;
        float sv = (acc[jj].x + acc[jj].y) + (acc[jj].z + acc[jj].w);
        out[lane * HH + jdx] = tanhf(sv + bias[jdx]);
    }
}

// ---------------- phase: attention for one (l, b) pair ----------------
struct SmemAttn {
    float qs[HH];
    float ssh[64];
    float wsh[64];
};
__device__ void attn_one(char* sm, int l, int b) {
    SmemAttn* s = (SmemAttn*)sm;
    int tid  = threadIdx.x;
    int warp = tid >> 5;
    int lane = tid & 31;

    s->qs[tid] = g_q[(l * BB + b) * HH + tid];
    __syncthreads();

    for (int sp = warp; sp < SS; sp += 16) {
        const float* krow = g_keysT + (b * SS + sp) * HH;
        float sum = 0.f;
        #pragma unroll
        for (int i = 0; i < 4; ++i) {
            float4 kv = *(const float4*)(krow  + lane * 4 + i * 128);
            float4 qv = *(const float4*)(s->qs + lane * 4 + i * 128);
            sum += kv.x*qv.x + kv.y*qv.y + kv.z*qv.z + kv.w*qv.w;
        }
        #pragma unroll
        for (int off = 16; off; off >>= 1)
            sum += __shfl_xor_sync(0xffffffffu, sum, off);
        if (lane == 0) s->ssh[sp] = sum / 7.0f;
    }
    __syncthreads();

    if (tid < 32) {
        float v0 = s->ssh[tid];
        float v1 = (tid + 32 < SS) ? s->ssh[tid + 32] : -3.4e38f;
        float m = fmaxf(v0, v1);
        #pragma unroll
        for (int off = 16; off; off >>= 1)
            m = fmaxf(m, __shfl_xor_sync(0xffffffffu, m, off));
        float e0 = expf(v0 - m);
        float e1 = (tid + 32 < SS) ? expf(v1 - m) : 0.f;
        float sm2 = e0 + e1;
        #pragma unroll
        for (int off = 16; off; off >>= 1)
            sm2 += __shfl_xor_sync(0xffffffffu, sm2, off);
        s->wsh[tid] = e0 / sm2;
        if (tid + 32 < SS) s->wsh[tid + 32] = e1 / sm2;
    }
    __syncthreads();

    {
        int d = tid;
        float a = 0.f;
        #pragma unroll
        for (int sp = 0; sp < SS; ++sp)
            a += s->wsh[sp] * g_valsT[(b * SS + sp) * HH + d];
        g_attn[(l * BB + b) * HH + d] = a;
    }
    __syncthreads();
}

// ---------------- the single persistent kernel ----------------
extern "C" __global__ void __launch_bounds__(NT, 1)
k_all(const float* __restrict__ img, const float* __restrict__ pooled,
      const float* __restrict__ embed,
      const float* __restrict__ Wq, const float* __restrict__ bq,
      const float* __restrict__ Wk, const float* __restrict__ bk,
      const float* __restrict__ Wv, const float* __restrict__ bv,
      const float* __restrict__ Wih, const float* __restrict__ Whh,
      const float* __restrict__ bih, const float* __restrict__ bhh,
      const float* __restrict__ projW, const float* __restrict__ projb,
      const float* __restrict__ hattW, const float* __restrict__ hattb,
      const int* __restrict__ sosp, float* __restrict__ res) {
    extern __shared__ __align__(16) char dynsm[];
    int wb = blockIdx.x;

    unsigned sense  = g_bar_flag;
    unsigned ssense = g_sub_flag;

    // phase A: keys/values + state init
    ph_kv_init(dynsm, img, pooled, embed, sosp[0], Wk, bk, Wv, bv);
    grid_bar(sense);

    // phase B: res[:, :, 0] from <SOS> embedding (no argmax)
    if (wb < LOGB)
        logits_phase(dynsm, g_pred0, projW, projb, res, wb * 96, 0, 0);
    grid_bar(sense);

    for (int i = 0; i < TT - 1; ++i) {
        // P1: LSTM layer 0
        if (wb < 128)
            lstm_phase(dynsm, wb, 0, (i == 0) ? 0 : 1, embed, Wih, Whh, bih, bhh);
        grid_bar(sense);

        // P2: LSTM layer 1; block 128 resets argmax accumulator
        if (wb < 128)
            lstm_phase(dynsm, wb, 1, 2, embed, Wih, Whh, bih, bhh);
        else if (wb == 128 && threadIdx.x < BB)
            g_amax[threadIdx.x] = 0ULL;
        grid_bar(sense);

        // P3 (split): blocks 0..104 logits; blocks 105..147 attention chain
        if (wb < LOGB) {
            logits_phase(dynsm, g_H1 + BB * HH, projW, projb, res,
                         wb * 96, i + 1, (i < TT - 2) ? 1 : 0);
        } else if (i < TT - 2) {
            int t = wb - ATT0;
            if (t < 32) gemm_phase<0>(dynsm, t, Wq, bq);
            sub_bar(ssense);
            {
                attn_one(dynsm, t >> 5, t & 31);
                int p2 = t + NSUB;
                if (p2 < 2 * BB) attn_one(dynsm, p2 >> 5, p2 & 31);
            }
            sub_bar(ssense);
            if (t < 32) gemm_phase<1>(dynsm, t, hattW, hattb);
        }
        grid_bar(sense);
    }
}

// ---------------- host launcher ----------------
extern "C" void kernel_launch(void* const* d_in, const int* in_sizes, int n_in,
                              void* d_out, int out_size) {
    const float* img    = (const float*)d_in[0];
    const float* pooled = (const float*)d_in[1];
    const float* embed  = (const float*)d_in[2];
    const float* Wq     = (const float*)d_in[3];
    const float* bq     = (const float*)d_in[4];
    const float* Wk     = (const float*)d_in[5];
    const float* bk     = (const float*)d_in[6];
    const float* Wv     = (const float*)d_in[7];
    const float* bv     = (const float*)d_in[8];
    const float* Wih    = (const float*)d_in[9];
    const float* Whh    = (const float*)d_in[10];
    const float* bih    = (const float*)d_in[11];
    const float* bhh    = (const float*)d_in[12];
    const float* projW  = (const float*)d_in[13];
    const float* projb  = (const float*)d_in[14];
    const float* hattW  = (const float*)d_in[15];
    const float* hattb  = (const float*)d_in[16];
    const int*   sosp   = (const int*)d_in[17];
    float* res = (float*)d_out;

    static int attr_set = 0;
    if (!attr_set) {
        cudaFuncSetAttribute(k_all, cudaFuncAttributeMaxDynamicSharedMemorySize, DYN_BYTES);
        attr_set = 1;
    }
    k_all<<<NB, NT, DYN_BYTES>>>(img, pooled, embed, Wq, bq, Wk, bk, Wv, bv,
                                 Wih, Whh, bih, bhh, projW, projb,
                                 hattW, hattb, sosp, res);
}